// round 13
// baseline (speedup 1.0000x reference)
#include <cuda_runtime.h>
#include <cstdint>

// out[512,128] = X[512, 1048576] @ W[1048576, 128]   fp32 in/out
//
// sm_103a pass: tcgen05 tf32 SS MMA, M=256 per CTA, 3-stage SMEM pipeline,
//   grid = 296 (148 k-slices x 2 M-groups), 256-col TMEM accumulator.
// generic compute_103 pass: mma.sync.m16n8k8.tf32 fallback (same launch shape).

#if defined(__CUDA_ARCH_FEAT_SM103_ALL)
#define USE_TCGEN05 1
#elif defined(__CUDA_ARCH_SPECIFIC__)
#if __CUDA_ARCH_SPECIFIC__ >= 1000
#define USE_TCGEN05 1
#else
#define USE_TCGEN05 0
#endif
#else
#define USE_TCGEN05 0
#endif

#define RED_LEN   1048576
#define M_ROWS    512
#define N_COLS    128
#define KTILE     32
#define NUM_SLOTS 148               // k-slices (scratch slots)
#define NUM_CTAS  296               // 148 k-slices x 2 M-groups
#define NTHREADS  512

// 32768 k-tiles = 148*221 + 60
#define TC_BASE 221
#define TC_REM  60

// ---- smem layout (both paths): 3 stages of 48KB ----
#define SM_TMEMPTR  0
#define SM_BARS     16               // 3 mbarriers @ 16,24,32
#define STAGE_BYTES 49152            // A 32KB (256 rows x 128B) + B 16KB
#define SM_STAGE0   1024
#define SMEM_TOTAL  (1024 + 3 * STAGE_BYTES)   // 148480

// idesc kind::tf32 SS cg1: c=F32(bit4), a=TF32(2<<7), b=TF32(2<<10),
// N>>3=16 (<<17), M>>4=8 (<<24), K-major A/B.  (per-MMA M=128)
#define IDESC_TF32 0x08200910u

__device__ float g_scratch[(size_t)NUM_SLOTS * M_ROWS * N_COLS];  // 38.8 MB
__device__ float g_scratch2[4 * (M_ROWS * N_COLS)];               // 1 MB

// ---------------- shared helpers ----------------
__device__ __forceinline__ uint32_t smem_u32(const void* p) {
    uint32_t a;
    asm("{ .reg .u64 t; cvta.to.shared.u64 t, %1; cvt.u32.u64 %0, t; }" : "=r"(a) : "l"(p));
    return a;
}
__device__ __forceinline__ uint32_t f2tf32(float x) {   // round-to-nearest tf32
    uint32_t u;
    asm("cvt.rna.tf32.f32 %0, %1;" : "=r"(u) : "f"(x));
    return u;
}

#if USE_TCGEN05
// ================= tcgen05 path helpers =================
__device__ __forceinline__ uint32_t elect_one() {
    uint32_t p;
    asm volatile("{ .reg .pred p; elect.sync _|p, 0xFFFFFFFF; selp.b32 %0, 1, 0, p; }" : "=r"(p));
    return p;
}
#define MBARRIER_INIT(addr, cnt) \
    asm volatile("mbarrier.init.shared.b64 [%0], %1;" :: "r"((uint32_t)(addr)), "r"((uint32_t)(cnt)) : "memory")

#define MBARRIER_WAIT_PARITY(mbar_smem_addr, phase_parity) do { \
    uint32_t _mbar = (uint32_t)(mbar_smem_addr); \
    uint32_t _parity = (uint32_t)(phase_parity); \
    uint32_t _done; \
    asm volatile( \
        "{\n\t.reg .pred p;\n\t" \
        "mbarrier.try_wait.parity.acquire.cta.shared::cta.b64 p, [%1], %2;\n\t" \
        "selp.b32 %0, 1, 0, p;\n\t}" \
        : "=r"(_done) : "r"(_mbar), "r"(_parity) : "memory"); \
    if (!_done) { \
        asm volatile( \
            "{\n\t.reg .pred P1;\n\t" \
            "WAIT_LOOP_%=:\n\t" \
            "mbarrier.try_wait.parity.acquire.cta.shared::cta.b64 P1, [%0], %1, 0x989680;\n\t" \
            "@P1 bra.uni WAIT_DONE_%=;\n\t" \
            "bra.uni WAIT_LOOP_%=;\n\t" \
            "WAIT_DONE_%=:\n\t}" \
            :: "r"(_mbar), "r"(_parity) : "memory"); \
    } \
} while (0)

#define TCGEN05_COMMIT(mbar) \
    asm volatile("tcgen05.commit.cta_group::1.mbarrier::arrive::one.shared::cluster.b64 [%0];" \
                 :: "r"((uint32_t)(mbar)) : "memory")
#define TCGEN05_FENCE_AFTER()  asm volatile("tcgen05.fence::after_thread_sync;" ::: "memory")
#define TCGEN05_FENCE_BEFORE() asm volatile("tcgen05.fence::before_thread_sync;" ::: "memory")
#define TCGEN05_WAIT_LD()      asm volatile("tcgen05.wait::ld.sync.aligned;" ::: "memory")

#define TCGEN05_LD_32X32B_X32(r, tmem_addr) \
    asm volatile( \
        "tcgen05.ld.sync.aligned.32x32b.x32.b32 " \
        "{%0, %1, %2, %3, %4, %5, %6, %7, " \
        " %8, %9, %10, %11, %12, %13, %14, %15, " \
        " %16, %17, %18, %19, %20, %21, %22, %23, " \
        " %24, %25, %26, %27, %28, %29, %30, %31}, [%32];" \
        : "=r"((r)[0]),  "=r"((r)[1]),  "=r"((r)[2]),  "=r"((r)[3]), \
          "=r"((r)[4]),  "=r"((r)[5]),  "=r"((r)[6]),  "=r"((r)[7]), \
          "=r"((r)[8]),  "=r"((r)[9]),  "=r"((r)[10]), "=r"((r)[11]), \
          "=r"((r)[12]), "=r"((r)[13]), "=r"((r)[14]), "=r"((r)[15]), \
          "=r"((r)[16]), "=r"((r)[17]), "=r"((r)[18]), "=r"((r)[19]), \
          "=r"((r)[20]), "=r"((r)[21]), "=r"((r)[22]), "=r"((r)[23]), \
          "=r"((r)[24]), "=r"((r)[25]), "=r"((r)[26]), "=r"((r)[27]), \
          "=r"((r)[28]), "=r"((r)[29]), "=r"((r)[30]), "=r"((r)[31]) \
        : "r"(tmem_addr))

// K-major SW128 smem descriptor: 128B rows, SBO=64, LBO=1, version=1
static constexpr uint64_t SMEM_DESC_BASE_SW128 =
    (uint64_t(2)  << 61) | (uint64_t(1) << 46) | (uint64_t(64) << 32) | (uint64_t(1) << 16);
#define MAKE_SMEM_DESC(base_addr) (SMEM_DESC_BASE_SW128 | ((uint64_t)((base_addr) >> 4) & 0x3FFF))

__device__ __forceinline__ void mma_tf32_ss(uint32_t d_tmem, uint64_t a_desc, uint64_t b_desc,
                                            uint32_t idesc, uint32_t enable_d) {
    asm volatile(
        "{\n\t.reg .pred p;\n\t"
        "setp.ne.u32 p, %4, 0;\n\t"
        "tcgen05.mma.cta_group::1.kind::tf32 [%0], %1, %2, %3, {%5,%5,%5,%5}, p;\n\t}"
        :: "r"(d_tmem), "l"(a_desc), "l"(b_desc), "r"(idesc), "r"(enable_d), "r"(0u)
        : "memory");
}

// Register-staged tile for M=256: A 4x float4, B 2x float4.
struct TileRegs {
    float4 a[4];
    float4 b[2];
};

__device__ __forceinline__ void tc_load(TileRegs& R, const float* __restrict__ X,
                                        const float* __restrict__ W, int kred0, int tid) {
    const int lid = tid & 31;
    const int wid = tid >> 5;
    {   // A: warp w covers rows [w*16, w*16+16) of 256; 128B coalesced per row
        const int c  = lid & 7;
        const int r0 = wid * 16 + (lid >> 3);
        #pragma unroll
        for (int i = 0; i < 4; ++i) {
            const int row = r0 + i * 4;
            R.a[i] = *reinterpret_cast<const float4*>(
                X + (size_t)row * RED_LEN + (size_t)kred0 + c * 4);
        }
    }
    {   // B: lanes n consecutive -> 128B coalesced; 4 k-rows per float4
        const int n   = tid & 127;
        const int kb0 = (tid >> 7);
        #pragma unroll
        for (int j = 0; j < 2; ++j) {
            const int kk = (kb0 + 4 * j) * 4;
            const float* wp = W + (size_t)(kred0 + kk) * N_COLS + n;
            R.b[j] = make_float4(wp[0], wp[N_COLS], wp[2 * N_COLS], wp[3 * N_COLS]);
        }
    }
}

// cvt.rna.tf32 + swizzled STS.  A: 2 subtiles x [128 x 128B] SW128;
// B: [128 n x 32 k] K-major SW128.  Conflict-free patterns (same as R11/12).
__device__ __forceinline__ void tc_store(const TileRegs& R, char* sA, char* sB, int tid) {
    const int lid = tid & 31;
    const int wid = tid >> 5;
    {
        const int c  = lid & 7;
        const int r0 = wid * 16 + (lid >> 3);
        #pragma unroll
        for (int i = 0; i < 4; ++i) {
            const int row = r0 + i * 4;
            uint4 tv;
            tv.x = f2tf32(R.a[i].x); tv.y = f2tf32(R.a[i].y);
            tv.z = f2tf32(R.a[i].z); tv.w = f2tf32(R.a[i].w);
            const int m = row >> 7, r = row & 127;
            *reinterpret_cast<uint4*>(sA + (m * 16384 + r * 128 + ((c ^ (r & 7)) << 4))) = tv;
        }
    }
    {
        const int n   = tid & 127;
        const int kb0 = (tid >> 7);
        #pragma unroll
        for (int j = 0; j < 2; ++j) {
            const int kb = kb0 + 4 * j;
            uint4 tv;
            tv.x = f2tf32(R.b[j].x); tv.y = f2tf32(R.b[j].y);
            tv.z = f2tf32(R.b[j].z); tv.w = f2tf32(R.b[j].w);
            *reinterpret_cast<uint4*>(sB + (n * 128 + ((kb ^ (n & 7)) << 4))) = tv;
        }
    }
    asm volatile("fence.proxy.async.shared::cta;" ::: "memory");
}
#else
// ================= mma.sync fallback helpers =================
__device__ __forceinline__ void cp16(uint32_t dst_smem, const void* src) {
    asm volatile("cp.async.cg.shared.global [%0], [%1], 16;" :: "r"(dst_smem), "l"(src) : "memory");
}
__device__ __forceinline__ float4 lds128(uint32_t addr) {
    float4 v;
    asm volatile("ld.shared.v4.f32 {%0,%1,%2,%3}, [%4];"
                 : "=f"(v.x), "=f"(v.y), "=f"(v.z), "=f"(v.w) : "r"(addr));
    return v;
}
__device__ __forceinline__ float lds32(uint32_t addr) {
    float v;
    asm volatile("ld.shared.f32 %0, [%1];" : "=f"(v) : "r"(addr));
    return v;
}
__device__ __forceinline__ void mma_tf32(float d[4], uint32_t a0, uint32_t a1, uint32_t a2, uint32_t a3,
                                         uint32_t b0, uint32_t b1) {
    asm volatile(
        "mma.sync.aligned.m16n8k8.row.col.f32.tf32.tf32.f32 "
        "{%0,%1,%2,%3}, {%4,%5,%6,%7}, {%8,%9}, {%0,%1,%2,%3};"
        : "+f"(d[0]), "+f"(d[1]), "+f"(d[2]), "+f"(d[3])
        : "r"(a0), "r"(a1), "r"(a2), "r"(a3), "r"(b0), "r"(b1));
}
#endif

// ================= unified GEMM kernel =================
__global__ void __launch_bounds__(NTHREADS, 1)
gemm_kernel(const float* __restrict__ X, const float* __restrict__ W) {
    extern __shared__ char smem[];
    const uint32_t sbase = smem_u32(smem);
    const int tid = threadIdx.x;
    const int wid = tid >> 5;
    const int lid = tid & 31;

    const int bid    = blockIdx.x;
    const int kslice = bid >> 1;        // 0..147 (scratch slot; W shared in L2 by mg pair)
    const int mg     = bid & 1;         // 0..1   (256 rows each)

#if USE_TCGEN05
    // ---------- tcgen05: M=256, 3-stage pipeline, 256-col TMEM ----------
    if (wid == 0) {
        asm volatile("tcgen05.alloc.cta_group::1.sync.aligned.shared::cta.b32 [%0], %1;"
                     :: "r"(sbase + SM_TMEMPTR), "r"(256u) : "memory");
        asm volatile("tcgen05.relinquish_alloc_permit.cta_group::1.sync.aligned;");
    }
    if (tid == 0) {
        MBARRIER_INIT(sbase + SM_BARS + 0,  1);
        MBARRIER_INIT(sbase + SM_BARS + 8,  1);
        MBARRIER_INIT(sbase + SM_BARS + 16, 1);
    }
    __syncthreads();
    uint32_t tmem;
    asm volatile("ld.shared.b32 %0, [%1];" : "=r"(tmem) : "r"(sbase + SM_TMEMPTR));

    const float* Xb = X + (size_t)(mg * 256) * RED_LEN;
    const int ntiles = TC_BASE + (kslice < TC_REM ? 1 : 0);   // strided split-K (>= 221)

    char* stg[3] = { smem + SM_STAGE0, smem + SM_STAGE0 + STAGE_BYTES,
                     smem + SM_STAGE0 + 2 * STAGE_BYTES };

    // prologue: tiles 0,1 -> stages 0,1; tile 2 -> registers
    TileRegs R;
    tc_load(R, Xb, W, kslice * KTILE, tid);               tc_store(R, stg[0], stg[0] + 32768, tid);
    tc_load(R, Xb, W, (kslice + NUM_SLOTS) * KTILE, tid); tc_store(R, stg[1], stg[1] + 32768, tid);
    tc_load(R, Xb, W, (kslice + 2 * NUM_SLOTS) * KTILE, tid);

    uint32_t ph[3] = {0, 0, 0};
    for (int t = 0; t < ntiles; ++t) {
        const int s = t % 3;
        __syncthreads();   // tile t's STS visible CTA-wide (+ proxy fence in tc_store)

        if (wid == 0) {
            TCGEN05_FENCE_AFTER();
            if (elect_one()) {
                const uint32_t sb = sbase + SM_STAGE0 + s * STAGE_BYTES;
                const uint64_t bd = MAKE_SMEM_DESC(sb + 32768);
                #pragma unroll
                for (int m = 0; m < 2; ++m) {
                    const uint64_t ad = MAKE_SMEM_DESC(sb + m * 16384);
                    #pragma unroll
                    for (int k = 0; k < 4; ++k) {   // K=8 per dispatch, +32B per step
                        mma_tf32_ss(tmem + m * 128, ad + 2 * k, bd + 2 * k,
                                    IDESC_TF32, (t > 0 || k > 0) ? 1u : 0u);
                    }
                }
                TCGEN05_COMMIT(sbase + SM_BARS + 8 * s);
            }
        }

        if (t + 2 < ntiles) {
            // stage (t+2)%3 was last read by MMA(t-1) -> usually already done:
            // MMA overlaps with this iteration's store/load instead of blocking it.
            const int u = (t + 2) % 3;
            if (t > 0) { MBARRIER_WAIT_PARITY(sbase + SM_BARS + 8 * u, ph[u]); ph[u] ^= 1; }
            tc_store(R, stg[u], stg[u] + 32768, tid);
            if (t + 3 < ntiles)
                tc_load(R, Xb, W, (kslice + (t + 3) * NUM_SLOTS) * KTILE, tid);
        }
    }

    // drain: exactly one outstanding commit per barrier
    #pragma unroll
    for (int u = 0; u < 3; ++u)
        MBARRIER_WAIT_PARITY(sbase + SM_BARS + 8 * u, ph[u]);
    TCGEN05_FENCE_AFTER();

    {   // epilogue: warp w -> m=(w>>2)&1, lane-group g=w&3, col-half = w>>3
        const int m    = (wid >> 2) & 1;
        const int g    = wid & 3;
        const int half = wid >> 3;
        const int row  = mg * 256 + m * 128 + g * 32 + lid;
        float* dst = g_scratch + (size_t)kslice * (M_ROWS * N_COLS) + (size_t)row * N_COLS;
        #pragma unroll
        for (int h = 0; h < 2; ++h) {
            const int c0 = half * 64 + h * 32;
            uint32_t r[32];
            TCGEN05_LD_32X32B_X32(r, tmem + m * 128 + c0);
            TCGEN05_WAIT_LD();
            #pragma unroll
            for (int j = 0; j < 32; j += 4) {
                float4 v = make_float4(__uint_as_float(r[j]),     __uint_as_float(r[j + 1]),
                                       __uint_as_float(r[j + 2]), __uint_as_float(r[j + 3]));
                *reinterpret_cast<float4*>(dst + c0 + j) = v;
            }
        }
    }

    TCGEN05_FENCE_BEFORE();
    __syncthreads();
    if (wid == 0) {
        asm volatile("tcgen05.dealloc.cta_group::1.sync.aligned.b32 %0, %1;" :: "r"(tmem), "r"(256u));
    }
#else
    // ---------- mma.sync fallback: 256x128 CTA tile, 16 warps 4m x 4n ----------
    const int wm = wid >> 2;
    const int wn = wid & 3;
    const int c  = lid & 3;
    const int r4 = lid >> 3;

    const int t0  = kslice * TC_BASE + (kslice < TC_REM ? kslice : TC_REM);
    const int cnt = TC_BASE + (kslice < TC_REM ? 1 : 0);
    const float* Xb = X + (size_t)(mg * 256) * RED_LEN;

    auto issue = [&](int stage, int tile) {
        const uint32_t sa = sbase + SM_STAGE0 + stage * STAGE_BYTES;
        const uint32_t sb = sa + 32768;
        const size_t kb = (size_t)(t0 + tile) * KTILE;
        #pragma unroll
        for (int i = 0; i < 4; ++i) {          // A: 2048 chunks (256 rows x 8)
            const int q = tid + NTHREADS * i;
            const int row = q >> 3, x = q & 7;
            cp16(sa + row * 128 + ((x ^ (row & 7)) << 4),
                 Xb + (size_t)row * RED_LEN + kb + x * 4);
        }
        #pragma unroll
        for (int i = 0; i < 2; ++i) {          // B: 1024 chunks (32 k-rows x 32)
            const int q = tid + NTHREADS * i;
            const int k = q >> 5, x = q & 31;
            cp16(sb + k * 512 + ((x ^ (((k >> 3) & 3) << 1)) << 4),
                 W + (kb + (size_t)k) * N_COLS + x * 4);
        }
    };

    #pragma unroll
    for (int s = 0; s < 2; ++s) {
        issue(s, s);
        asm volatile("cp.async.commit_group;" ::: "memory");
    }

    float d[4][4][4];
    #pragma unroll
    for (int a = 0; a < 4; ++a)
        #pragma unroll
        for (int b = 0; b < 4; ++b)
            #pragma unroll
            for (int e = 0; e < 4; ++e) d[a][b][e] = 0.f;

    int st = 0;
    for (int t = 0; t < cnt; ++t) {
        asm volatile("cp.async.wait_group 1;" ::: "memory");
        __syncthreads();

        const uint32_t sa = sbase + SM_STAGE0 + st * STAGE_BYTES;
        const uint32_t sb = sa + 32768;

        uint32_t bf[4][4][2];
        #pragma unroll
        for (int nt = 0; nt < 4; ++nt) {
            const int n = wn * 32 + nt * 8 + r4;
            const uint32_t baddr = sb + (((n >> 2) ^ (2 * c)) << 4) + (n & 3) * 4;
            #pragma unroll
            for (int j = 0; j < 4; ++j) {
                const int k0 = 8 * c + 2 * j;
                bf[nt][j][0] = f2tf32(lds32(baddr + k0 * 512));
                bf[nt][j][1] = f2tf32(lds32(baddr + (k0 + 1) * 512));
            }
        }

        const uint32_t ch0 = ((2 * c) ^ r4) << 4;
        const uint32_t ch1 = ((2 * c + 1) ^ r4) << 4;
        #pragma unroll
        for (int mt = 0; mt < 4; ++mt) {
            const int R0 = wm * 64 + mt * 16 + r4;
            const uint32_t ab0 = sa + R0 * 128;
            const uint32_t ab1 = ab0 + 8 * 128;
            const float4 p0 = lds128(ab0 + ch0);
            const float4 p1 = lds128(ab0 + ch1);
            const float4 q0 = lds128(ab1 + ch0);
            const float4 q1 = lds128(ab1 + ch1);
            uint32_t a0r[8] = { f2tf32(p0.x), f2tf32(p0.y), f2tf32(p0.z), f2tf32(p0.w),
                                f2tf32(p1.x), f2tf32(p1.y), f2tf32(p1.z), f2tf32(p1.w) };
            uint32_t a1r[8] = { f2tf32(q0.x), f2tf32(q0.y), f2tf32(q0.z), f2tf32(q0.w),
                                f2tf32(q1.x), f2tf32(q1.y), f2tf32(q1.z), f2tf32(q1.w) };
            #pragma unroll
            for (int j = 0; j < 4; ++j) {
                const uint32_t A0 = a0r[2 * j],     A1 = a1r[2 * j];
                const uint32_t A2 = a0r[2 * j + 1], A3 = a1r[2 * j + 1];
                #pragma unroll
                for (int nt = 0; nt < 4; ++nt)
                    mma_tf32(d[mt][nt], A0, A1, A2, A3, bf[nt][j][0], bf[nt][j][1]);
            }
        }

        __syncthreads();
        if (t + 2 < cnt) {
            int s2 = st + 2; if (s2 >= 3) s2 -= 3;
            issue(s2, t + 2);
        }
        asm volatile("cp.async.commit_group;" ::: "memory");
        if (++st == 3) st = 0;
    }

    float* outp = g_scratch + (size_t)kslice * (M_ROWS * N_COLS);
    #pragma unroll
    for (int mt = 0; mt < 4; ++mt) {
        #pragma unroll
        for (int nt = 0; nt < 4; ++nt) {
            const int row = mg * 256 + wm * 64 + mt * 16 + r4;
            const int col = wn * 32 + nt * 8 + 2 * c;
            float2 v0 = make_float2(d[mt][nt][0], d[mt][nt][1]);
            float2 v1 = make_float2(d[mt][nt][2], d[mt][nt][3]);
            *reinterpret_cast<float2*>(outp + (size_t)row * N_COLS + col)       = v0;
            *reinterpret_cast<float2*>(outp + (size_t)(row + 8) * N_COLS + col) = v1;
        }
    }
#endif
}

// ---------------- deterministic two-phase reduction ----------------
// Phase 1: 65536 threads; thread (i4, q) sums 37 of 148 slots (148 = 4*37).
__global__ void reduce_phase1() {
    const int idx = blockIdx.x * blockDim.x + threadIdx.x;   // 0 .. 65535
    const int i4  = idx & 16383;
    const int q   = idx >> 14;                               // 0..3
    const float4* src = reinterpret_cast<const float4*>(g_scratch);
    float4 acc = make_float4(0.f, 0.f, 0.f, 0.f);
    const int g0 = q * 37;
    #pragma unroll 4
    for (int g = g0; g < g0 + 37; ++g) {
        const float4 v = src[(size_t)g * (M_ROWS * N_COLS / 4) + i4];
        acc.x += v.x; acc.y += v.y; acc.z += v.z; acc.w += v.w;
    }
    reinterpret_cast<float4*>(g_scratch2)[(size_t)q * (M_ROWS * N_COLS / 4) + i4] = acc;
}

// Phase 2: sum the 4 intermediates.
__global__ void reduce_phase2(float* __restrict__ out) {
    const int i4 = blockIdx.x * blockDim.x + threadIdx.x;    // 0 .. 16383
    const float4* s2 = reinterpret_cast<const float4*>(g_scratch2);
    const int Q = M_ROWS * N_COLS / 4;
    float4 a = s2[i4], b = s2[Q + i4], c = s2[2 * Q + i4], d = s2[3 * Q + i4];
    float4 acc = make_float4(a.x + b.x + c.x + d.x, a.y + b.y + c.y + d.y,
                             a.z + b.z + c.z + d.z, a.w + b.w + c.w + d.w);
    reinterpret_cast<float4*>(out)[i4] = acc;
}

extern "C" void kernel_launch(void* const* d_in, const int* in_sizes, int n_in,
                              void* d_out, int out_size) {
    const float* X = (const float*)d_in[0];   // [512, 1024, 1024]
    const float* W = (const float*)d_in[1];   // [1024, 1024, 128]
    float* out = (float*)d_out;               // [512, 128]

    cudaFuncSetAttribute(gemm_kernel, cudaFuncAttributeMaxDynamicSharedMemorySize, SMEM_TOTAL);
    gemm_kernel<<<NUM_CTAS, NTHREADS, SMEM_TOTAL>>>(X, W);
    reduce_phase1<<<(4 * M_ROWS * N_COLS / 4) / 256, 256>>>();
    reduce_phase2<<<(M_ROWS * N_COLS / 4) / 256, 256>>>(out);
}

// round 14
// speedup vs baseline: 1.1699x; 1.1699x over previous
#include <cuda_runtime.h>
#include <cstdint>

// out[512,128] = X[512, 1048576] @ W[1048576, 128]   fp32 in/out
//
// sm_103a pass: tcgen05 tf32 SS MMA, M=256 per CTA, 2-stage SMEM pipeline,
//   grid = 296 (148 k-slices x 2 M-groups), occupancy 2 CTAs/SM (96KB smem,
//   256-col TMEM each -> 512-col budget exactly).  Latency gaps of one CTA
//   are covered by the co-resident CTA.
// generic compute_103 pass: mma.sync.m16n8k8.tf32 fallback (2-stage).

#if defined(__CUDA_ARCH_FEAT_SM103_ALL)
#define USE_TCGEN05 1
#elif defined(__CUDA_ARCH_SPECIFIC__)
#if __CUDA_ARCH_SPECIFIC__ >= 1000
#define USE_TCGEN05 1
#else
#define USE_TCGEN05 0
#endif
#else
#define USE_TCGEN05 0
#endif

#if USE_TCGEN05
#define MIN_CTAS_SM 2
#else
#define MIN_CTAS_SM 1
#endif

#define RED_LEN   1048576
#define M_ROWS    512
#define N_COLS    128
#define KTILE     32
#define NUM_SLOTS 148               // k-slices (scratch slots)
#define NUM_CTAS  296               // 148 k-slices x 2 M-groups
#define NTHREADS  512

// 32768 k-tiles = 148*221 + 60
#define TC_BASE 221
#define TC_REM  60

// ---- smem layout (both paths): 2 stages of 48KB ----
#define SM_TMEMPTR  0
#define SM_BARS     16               // 2 mbarriers @ 16,24
#define STAGE_BYTES 49152            // A 32KB (256 rows x 128B) + B 16KB
#define SM_STAGE0   1024
#define SMEM_TOTAL  (1024 + 2 * STAGE_BYTES)   // 99328 -> 2 CTAs/SM

// idesc kind::tf32 SS cg1: c=F32(bit4), a=TF32(2<<7), b=TF32(2<<10),
// N>>3=16 (<<17), M>>4=8 (<<24), K-major A/B.  (per-MMA M=128)
#define IDESC_TF32 0x08200910u

__device__ float g_scratch[(size_t)NUM_SLOTS * M_ROWS * N_COLS];  // 38.8 MB
__device__ float g_scratch2[4 * (M_ROWS * N_COLS)];               // 1 MB

// ---------------- shared helpers ----------------
__device__ __forceinline__ uint32_t smem_u32(const void* p) {
    uint32_t a;
    asm("{ .reg .u64 t; cvta.to.shared.u64 t, %1; cvt.u32.u64 %0, t; }" : "=r"(a) : "l"(p));
    return a;
}
__device__ __forceinline__ uint32_t f2tf32(float x) {   // round-to-nearest tf32
    uint32_t u;
    asm("cvt.rna.tf32.f32 %0, %1;" : "=r"(u) : "f"(x));
    return u;
}

#if USE_TCGEN05
// ================= tcgen05 path helpers =================
__device__ __forceinline__ uint32_t elect_one() {
    uint32_t p;
    asm volatile("{ .reg .pred p; elect.sync _|p, 0xFFFFFFFF; selp.b32 %0, 1, 0, p; }" : "=r"(p));
    return p;
}
#define MBARRIER_INIT(addr, cnt) \
    asm volatile("mbarrier.init.shared.b64 [%0], %1;" :: "r"((uint32_t)(addr)), "r"((uint32_t)(cnt)) : "memory")

#define MBARRIER_WAIT_PARITY(mbar_smem_addr, phase_parity) do { \
    uint32_t _mbar = (uint32_t)(mbar_smem_addr); \
    uint32_t _parity = (uint32_t)(phase_parity); \
    uint32_t _done; \
    asm volatile( \
        "{\n\t.reg .pred p;\n\t" \
        "mbarrier.try_wait.parity.acquire.cta.shared::cta.b64 p, [%1], %2;\n\t" \
        "selp.b32 %0, 1, 0, p;\n\t}" \
        : "=r"(_done) : "r"(_mbar), "r"(_parity) : "memory"); \
    if (!_done) { \
        asm volatile( \
            "{\n\t.reg .pred P1;\n\t" \
            "WAIT_LOOP_%=:\n\t" \
            "mbarrier.try_wait.parity.acquire.cta.shared::cta.b64 P1, [%0], %1, 0x989680;\n\t" \
            "@P1 bra.uni WAIT_DONE_%=;\n\t" \
            "bra.uni WAIT_LOOP_%=;\n\t" \
            "WAIT_DONE_%=:\n\t}" \
            :: "r"(_mbar), "r"(_parity) : "memory"); \
    } \
} while (0)

#define TCGEN05_COMMIT(mbar) \
    asm volatile("tcgen05.commit.cta_group::1.mbarrier::arrive::one.shared::cluster.b64 [%0];" \
                 :: "r"((uint32_t)(mbar)) : "memory")
#define TCGEN05_FENCE_AFTER()  asm volatile("tcgen05.fence::after_thread_sync;" ::: "memory")
#define TCGEN05_FENCE_BEFORE() asm volatile("tcgen05.fence::before_thread_sync;" ::: "memory")
#define TCGEN05_WAIT_LD()      asm volatile("tcgen05.wait::ld.sync.aligned;" ::: "memory")

#define TCGEN05_LD_32X32B_X32(r, tmem_addr) \
    asm volatile( \
        "tcgen05.ld.sync.aligned.32x32b.x32.b32 " \
        "{%0, %1, %2, %3, %4, %5, %6, %7, " \
        " %8, %9, %10, %11, %12, %13, %14, %15, " \
        " %16, %17, %18, %19, %20, %21, %22, %23, " \
        " %24, %25, %26, %27, %28, %29, %30, %31}, [%32];" \
        : "=r"((r)[0]),  "=r"((r)[1]),  "=r"((r)[2]),  "=r"((r)[3]), \
          "=r"((r)[4]),  "=r"((r)[5]),  "=r"((r)[6]),  "=r"((r)[7]), \
          "=r"((r)[8]),  "=r"((r)[9]),  "=r"((r)[10]), "=r"((r)[11]), \
          "=r"((r)[12]), "=r"((r)[13]), "=r"((r)[14]), "=r"((r)[15]), \
          "=r"((r)[16]), "=r"((r)[17]), "=r"((r)[18]), "=r"((r)[19]), \
          "=r"((r)[20]), "=r"((r)[21]), "=r"((r)[22]), "=r"((r)[23]), \
          "=r"((r)[24]), "=r"((r)[25]), "=r"((r)[26]), "=r"((r)[27]), \
          "=r"((r)[28]), "=r"((r)[29]), "=r"((r)[30]), "=r"((r)[31]) \
        : "r"(tmem_addr))

// K-major SW128 smem descriptor: 128B rows, SBO=64, LBO=1, version=1
static constexpr uint64_t SMEM_DESC_BASE_SW128 =
    (uint64_t(2)  << 61) | (uint64_t(1) << 46) | (uint64_t(64) << 32) | (uint64_t(1) << 16);
#define MAKE_SMEM_DESC(base_addr) (SMEM_DESC_BASE_SW128 | ((uint64_t)((base_addr) >> 4) & 0x3FFF))

__device__ __forceinline__ void mma_tf32_ss(uint32_t d_tmem, uint64_t a_desc, uint64_t b_desc,
                                            uint32_t idesc, uint32_t enable_d) {
    asm volatile(
        "{\n\t.reg .pred p;\n\t"
        "setp.ne.u32 p, %4, 0;\n\t"
        "tcgen05.mma.cta_group::1.kind::tf32 [%0], %1, %2, %3, {%5,%5,%5,%5}, p;\n\t}"
        :: "r"(d_tmem), "l"(a_desc), "l"(b_desc), "r"(idesc), "r"(enable_d), "r"(0u)
        : "memory");
}

// Register-staged tile for M=256: A 4x float4, B 2x float4 (24 regs).
struct TileRegs {
    float4 a[4];
    float4 b[2];
};

__device__ __forceinline__ void tc_load(TileRegs& R, const float* __restrict__ X,
                                        const float* __restrict__ W, int kred0, int tid) {
    const int lid = tid & 31;
    const int wid = tid >> 5;
    {   // A: warp w covers rows [w*16, w*16+16) of 256; 128B coalesced per row
        const int c  = lid & 7;
        const int r0 = wid * 16 + (lid >> 3);
        #pragma unroll
        for (int i = 0; i < 4; ++i) {
            const int row = r0 + i * 4;
            R.a[i] = *reinterpret_cast<const float4*>(
                X + (size_t)row * RED_LEN + (size_t)kred0 + c * 4);
        }
    }
    {   // B: lanes n consecutive -> 128B coalesced; 4 k-rows per float4
        const int n   = tid & 127;
        const int kb0 = (tid >> 7);
        #pragma unroll
        for (int j = 0; j < 2; ++j) {
            const int kk = (kb0 + 4 * j) * 4;
            const float* wp = W + (size_t)(kred0 + kk) * N_COLS + n;
            R.b[j] = make_float4(wp[0], wp[N_COLS], wp[2 * N_COLS], wp[3 * N_COLS]);
        }
    }
}

// cvt.rna.tf32 + swizzled STS.  A: 2 subtiles x [128 x 128B] SW128;
// B: [128 n x 32 k] K-major SW128.  Conflict-free patterns.
__device__ __forceinline__ void tc_store(const TileRegs& R, char* sA, char* sB, int tid) {
    const int lid = tid & 31;
    const int wid = tid >> 5;
    {
        const int c  = lid & 7;
        const int r0 = wid * 16 + (lid >> 3);
        #pragma unroll
        for (int i = 0; i < 4; ++i) {
            const int row = r0 + i * 4;
            uint4 tv;
            tv.x = f2tf32(R.a[i].x); tv.y = f2tf32(R.a[i].y);
            tv.z = f2tf32(R.a[i].z); tv.w = f2tf32(R.a[i].w);
            const int m = row >> 7, r = row & 127;
            *reinterpret_cast<uint4*>(sA + (m * 16384 + r * 128 + ((c ^ (r & 7)) << 4))) = tv;
        }
    }
    {
        const int n   = tid & 127;
        const int kb0 = (tid >> 7);
        #pragma unroll
        for (int j = 0; j < 2; ++j) {
            const int kb = kb0 + 4 * j;
            uint4 tv;
            tv.x = f2tf32(R.b[j].x); tv.y = f2tf32(R.b[j].y);
            tv.z = f2tf32(R.b[j].z); tv.w = f2tf32(R.b[j].w);
            *reinterpret_cast<uint4*>(sB + (n * 128 + ((kb ^ (n & 7)) << 4))) = tv;
        }
    }
    asm volatile("fence.proxy.async.shared::cta;" ::: "memory");
}
#else
// ================= mma.sync fallback helpers =================
__device__ __forceinline__ void cp16(uint32_t dst_smem, const void* src) {
    asm volatile("cp.async.cg.shared.global [%0], [%1], 16;" :: "r"(dst_smem), "l"(src) : "memory");
}
__device__ __forceinline__ float4 lds128(uint32_t addr) {
    float4 v;
    asm volatile("ld.shared.v4.f32 {%0,%1,%2,%3}, [%4];"
                 : "=f"(v.x), "=f"(v.y), "=f"(v.z), "=f"(v.w) : "r"(addr));
    return v;
}
__device__ __forceinline__ float lds32(uint32_t addr) {
    float v;
    asm volatile("ld.shared.f32 %0, [%1];" : "=f"(v) : "r"(addr));
    return v;
}
__device__ __forceinline__ void mma_tf32(float d[4], uint32_t a0, uint32_t a1, uint32_t a2, uint32_t a3,
                                         uint32_t b0, uint32_t b1) {
    asm volatile(
        "mma.sync.aligned.m16n8k8.row.col.f32.tf32.tf32.f32 "
        "{%0,%1,%2,%3}, {%4,%5,%6,%7}, {%8,%9}, {%0,%1,%2,%3};"
        : "+f"(d[0]), "+f"(d[1]), "+f"(d[2]), "+f"(d[3])
        : "r"(a0), "r"(a1), "r"(a2), "r"(a3), "r"(b0), "r"(b1));
}
#endif

// ================= unified GEMM kernel =================
__global__ void __launch_bounds__(NTHREADS, MIN_CTAS_SM)
gemm_kernel(const float* __restrict__ X, const float* __restrict__ W) {
    extern __shared__ char smem[];
    const uint32_t sbase = smem_u32(smem);
    const int tid = threadIdx.x;
    const int wid = tid >> 5;
    const int lid = tid & 31;

    const int bid    = blockIdx.x;
    const int kslice = bid >> 1;        // 0..147 (scratch slot)
    const int mg     = bid & 1;         // 0..1   (256 rows each)

#if USE_TCGEN05
    // ---------- tcgen05: M=256, 2-stage pipeline, 256-col TMEM, occ=2 ----------
    if (wid == 0) {
        asm volatile("tcgen05.alloc.cta_group::1.sync.aligned.shared::cta.b32 [%0], %1;"
                     :: "r"(sbase + SM_TMEMPTR), "r"(256u) : "memory");
        asm volatile("tcgen05.relinquish_alloc_permit.cta_group::1.sync.aligned;");
    }
    if (tid == 0) {
        MBARRIER_INIT(sbase + SM_BARS + 0, 1);
        MBARRIER_INIT(sbase + SM_BARS + 8, 1);
    }
    __syncthreads();
    uint32_t tmem;
    asm volatile("ld.shared.b32 %0, [%1];" : "=r"(tmem) : "r"(sbase + SM_TMEMPTR));

    const float* Xb = X + (size_t)(mg * 256) * RED_LEN;
    const int ntiles = TC_BASE + (kslice < TC_REM ? 1 : 0);   // strided split-K (>= 221)

    char* stg0 = smem + SM_STAGE0;
    char* stg1 = smem + SM_STAGE0 + STAGE_BYTES;

    // prologue: tiles 0,1 -> stages 0,1; tile 2 -> registers
    TileRegs R;
    tc_load(R, Xb, W, kslice * KTILE, tid);               tc_store(R, stg0, stg0 + 32768, tid);
    tc_load(R, Xb, W, (kslice + NUM_SLOTS) * KTILE, tid); tc_store(R, stg1, stg1 + 32768, tid);
    tc_load(R, Xb, W, (kslice + 2 * NUM_SLOTS) * KTILE, tid);

    uint32_t ph0 = 0, ph1 = 0;
    for (int t = 0; t < ntiles; ++t) {
        const int s = t & 1;
        __syncthreads();   // tile t's STS visible CTA-wide (+ proxy fence in tc_store)

        if (wid == 0) {
            TCGEN05_FENCE_AFTER();
            if (elect_one()) {
                const uint32_t sb = sbase + SM_STAGE0 + s * STAGE_BYTES;
                const uint64_t bd = MAKE_SMEM_DESC(sb + 32768);
                #pragma unroll
                for (int m = 0; m < 2; ++m) {
                    const uint64_t ad = MAKE_SMEM_DESC(sb + m * 16384);
                    #pragma unroll
                    for (int k = 0; k < 4; ++k) {   // K=8 per dispatch, +32B per step
                        mma_tf32_ss(tmem + m * 128, ad + 2 * k, bd + 2 * k,
                                    IDESC_TF32, (t > 0 || k > 0) ? 1u : 0u);
                    }
                }
                TCGEN05_COMMIT(sbase + SM_BARS + 8 * s);
            }
        }

        if (t + 2 < ntiles) {
            // wait for MMA(t) (stage s consumed), then store prefetched t+2;
            // the co-resident CTA covers this stall.
            if (s) { MBARRIER_WAIT_PARITY(sbase + SM_BARS + 8, ph1); ph1 ^= 1; }
            else   { MBARRIER_WAIT_PARITY(sbase + SM_BARS + 0, ph0); ph0 ^= 1; }
            tc_store(R, s ? stg1 : stg0, (s ? stg1 : stg0) + 32768, tid);
            if (t + 3 < ntiles)
                tc_load(R, Xb, W, (kslice + (t + 3) * NUM_SLOTS) * KTILE, tid);
        }
    }

    MBARRIER_WAIT_PARITY(sbase + SM_BARS + 0, ph0);
    MBARRIER_WAIT_PARITY(sbase + SM_BARS + 8, ph1);
    TCGEN05_FENCE_AFTER();

    {   // epilogue: warp w -> m=(w>>2)&1, lane-group g=w&3, col-half = w>>3
        const int m    = (wid >> 2) & 1;
        const int g    = wid & 3;
        const int half = wid >> 3;
        const int row  = mg * 256 + m * 128 + g * 32 + lid;
        float* dst = g_scratch + (size_t)kslice * (M_ROWS * N_COLS) + (size_t)row * N_COLS;
        #pragma unroll
        for (int h = 0; h < 2; ++h) {
            const int c0 = half * 64 + h * 32;
            uint32_t r[32];
            TCGEN05_LD_32X32B_X32(r, tmem + m * 128 + c0);
            TCGEN05_WAIT_LD();
            #pragma unroll
            for (int j = 0; j < 32; j += 4) {
                float4 v = make_float4(__uint_as_float(r[j]),     __uint_as_float(r[j + 1]),
                                       __uint_as_float(r[j + 2]), __uint_as_float(r[j + 3]));
                *reinterpret_cast<float4*>(dst + c0 + j) = v;
            }
        }
    }

    TCGEN05_FENCE_BEFORE();
    __syncthreads();
    if (wid == 0) {
        asm volatile("tcgen05.dealloc.cta_group::1.sync.aligned.b32 %0, %1;" :: "r"(tmem), "r"(256u));
    }
#else
    // ---------- mma.sync fallback: 256x128 CTA tile, 2-stage cp.async ----------
    const int wm = wid >> 2;
    const int wn = wid & 3;
    const int c  = lid & 3;
    const int r4 = lid >> 3;

    const int t0  = kslice * TC_BASE + (kslice < TC_REM ? kslice : TC_REM);
    const int cnt = TC_BASE + (kslice < TC_REM ? 1 : 0);
    const float* Xb = X + (size_t)(mg * 256) * RED_LEN;

    auto issue = [&](int stage, int tile) {
        const uint32_t sa = sbase + SM_STAGE0 + stage * STAGE_BYTES;
        const uint32_t sb = sa + 32768;
        const size_t kb = (size_t)(t0 + tile) * KTILE;
        #pragma unroll
        for (int i = 0; i < 4; ++i) {          // A: 2048 chunks (256 rows x 8)
            const int q = tid + NTHREADS * i;
            const int row = q >> 3, x = q & 7;
            cp16(sa + row * 128 + ((x ^ (row & 7)) << 4),
                 Xb + (size_t)row * RED_LEN + kb + x * 4);
        }
        #pragma unroll
        for (int i = 0; i < 2; ++i) {          // B: 1024 chunks (32 k-rows x 32)
            const int q = tid + NTHREADS * i;
            const int k = q >> 5, x = q & 31;
            cp16(sb + k * 512 + ((x ^ (((k >> 3) & 3) << 1)) << 4),
                 W + (kb + (size_t)k) * N_COLS + x * 4);
        }
    };

    #pragma unroll
    for (int s = 0; s < 2; ++s) {
        issue(s, s);
        asm volatile("cp.async.commit_group;" ::: "memory");
    }

    float d[4][4][4];
    #pragma unroll
    for (int a = 0; a < 4; ++a)
        #pragma unroll
        for (int b = 0; b < 4; ++b)
            #pragma unroll
            for (int e = 0; e < 4; ++e) d[a][b][e] = 0.f;

    for (int t = 0; t < cnt; ++t) {
        asm volatile("cp.async.wait_group 1;" ::: "memory");
        __syncthreads();

        const uint32_t sa = sbase + SM_STAGE0 + (t & 1) * STAGE_BYTES;
        const uint32_t sb = sa + 32768;

        uint32_t bf[4][4][2];
        #pragma unroll
        for (int nt = 0; nt < 4; ++nt) {
            const int n = wn * 32 + nt * 8 + r4;
            const uint32_t baddr = sb + (((n >> 2) ^ (2 * c)) << 4) + (n & 3) * 4;
            #pragma unroll
            for (int j = 0; j < 4; ++j) {
                const int k0 = 8 * c + 2 * j;
                bf[nt][j][0] = f2tf32(lds32(baddr + k0 * 512));
                bf[nt][j][1] = f2tf32(lds32(baddr + (k0 + 1) * 512));
            }
        }

        const uint32_t ch0 = ((2 * c) ^ r4) << 4;
        const uint32_t ch1 = ((2 * c + 1) ^ r4) << 4;
        #pragma unroll
        for (int mt = 0; mt < 4; ++mt) {
            const int R0 = wm * 64 + mt * 16 + r4;
            const uint32_t ab0 = sa + R0 * 128;
            const uint32_t ab1 = ab0 + 8 * 128;
            const float4 p0 = lds128(ab0 + ch0);
            const float4 p1 = lds128(ab0 + ch1);
            const float4 q0 = lds128(ab1 + ch0);
            const float4 q1 = lds128(ab1 + ch1);
            uint32_t a0r[8] = { f2tf32(p0.x), f2tf32(p0.y), f2tf32(p0.z), f2tf32(p0.w),
                                f2tf32(p1.x), f2tf32(p1.y), f2tf32(p1.z), f2tf32(p1.w) };
            uint32_t a1r[8] = { f2tf32(q0.x), f2tf32(q0.y), f2tf32(q0.z), f2tf32(q0.w),
                                f2tf32(q1.x), f2tf32(q1.y), f2tf32(q1.z), f2tf32(q1.w) };
            #pragma unroll
            for (int j = 0; j < 4; ++j) {
                const uint32_t A0 = a0r[2 * j],     A1 = a1r[2 * j];
                const uint32_t A2 = a0r[2 * j + 1], A3 = a1r[2 * j + 1];
                #pragma unroll
                for (int nt = 0; nt < 4; ++nt)
                    mma_tf32(d[mt][nt], A0, A1, A2, A3, bf[nt][j][0], bf[nt][j][1]);
            }
        }

        __syncthreads();   // all reads of stage t&1 done before refill
        if (t + 2 < cnt) issue(t & 1, t + 2);
        asm volatile("cp.async.commit_group;" ::: "memory");
    }

    float* outp = g_scratch + (size_t)kslice * (M_ROWS * N_COLS);
    #pragma unroll
    for (int mt = 0; mt < 4; ++mt) {
        #pragma unroll
        for (int nt = 0; nt < 4; ++nt) {
            const int row = mg * 256 + wm * 64 + mt * 16 + r4;
            const int col = wn * 32 + nt * 8 + 2 * c;
            float2 v0 = make_float2(d[mt][nt][0], d[mt][nt][1]);
            float2 v1 = make_float2(d[mt][nt][2], d[mt][nt][3]);
            *reinterpret_cast<float2*>(outp + (size_t)row * N_COLS + col)       = v0;
            *reinterpret_cast<float2*>(outp + (size_t)(row + 8) * N_COLS + col) = v1;
        }
    }
#endif
}

// ---------------- deterministic two-phase reduction ----------------
__global__ void reduce_phase1() {
    const int idx = blockIdx.x * blockDim.x + threadIdx.x;   // 0 .. 65535
    const int i4  = idx & 16383;
    const int q   = idx >> 14;                               // 0..3
    const float4* src = reinterpret_cast<const float4*>(g_scratch);
    float4 acc = make_float4(0.f, 0.f, 0.f, 0.f);
    const int g0 = q * 37;
    #pragma unroll 4
    for (int g = g0; g < g0 + 37; ++g) {
        const float4 v = src[(size_t)g * (M_ROWS * N_COLS / 4) + i4];
        acc.x += v.x; acc.y += v.y; acc.z += v.z; acc.w += v.w;
    }
    reinterpret_cast<float4*>(g_scratch2)[(size_t)q * (M_ROWS * N_COLS / 4) + i4] = acc;
}

__global__ void reduce_phase2(float* __restrict__ out) {
    const int i4 = blockIdx.x * blockDim.x + threadIdx.x;    // 0 .. 16383
    const float4* s2 = reinterpret_cast<const float4*>(g_scratch2);
    const int Q = M_ROWS * N_COLS / 4;
    float4 a = s2[i4], b = s2[Q + i4], c = s2[2 * Q + i4], d = s2[3 * Q + i4];
    float4 acc = make_float4(a.x + b.x + c.x + d.x, a.y + b.y + c.y + d.y,
                             a.z + b.z + c.z + d.z, a.w + b.w + c.w + d.w);
    reinterpret_cast<float4*>(out)[i4] = acc;
}

extern "C" void kernel_launch(void* const* d_in, const int* in_sizes, int n_in,
                              void* d_out, int out_size) {
    const float* X = (const float*)d_in[0];   // [512, 1024, 1024]
    const float* W = (const float*)d_in[1];   // [1024, 1024, 128]
    float* out = (float*)d_out;               // [512, 128]

    cudaFuncSetAttribute(gemm_kernel, cudaFuncAttributeMaxDynamicSharedMemorySize, SMEM_TOTAL);
    gemm_kernel<<<NUM_CTAS, NTHREADS, SMEM_TOTAL>>>(X, W);
    reduce_phase1<<<(4 * M_ROWS * N_COLS / 4) / 256, 256>>>();
    reduce_phase2<<<(M_ROWS * N_COLS / 4) / 256, 256>>>(out);
}